// round 9
// baseline (speedup 1.0000x reference)
#include <cuda_runtime.h>
#include <cuda_fp16.h>

// CompetitiveLayer, fully fused into ONE persistent kernel.
//   21 x { AF = AT/(1+K@BF);  BF = BT/(1+AF@K) },  K = param^2 (fp16 copy),
//   then C = param^2 * AF[:,None] * BF[None,:]  (exact fp32 K for the output).
//
// R8 evidence: 64 graph nodes cost ~5.7us/iteration in launch overhead
// (finalize_bf: 4.7us for 256KB of work). This version replaces every kernel
// boundary with a ~0.5us software grid barrier. Cross-block vectors (AF, BF,
// tmp) move through L2 only (__ldcg/__stcg) since L1 is not coherent across
// SMs within a launch.

#define N        4096
#define NITER    21
#define NBLK     256
#define NTHR     256
#define ROW_CHUNKS 16
#define CHUNK_ROWS (N / ROW_CHUNKS)   // 256
#define COL_TILE   256

// Scratch — __device__ globals (no cudaMalloc allowed)
__device__ __half   g_Kh[(size_t)N * N];     // fp16 param^2, 32 MB, L2-resident
__device__ float    g_AF[N];
__device__ float    g_BF[N];
__device__ float    g_tmp[ROW_CHUNKS * N];
__device__ unsigned g_bar_count[32];          // [0] used; padded to own line
__device__ unsigned g_bar_gen[32];            // [0] used; separate line

__global__ __launch_bounds__(NTHR, 2)
void competitive_solve_kernel(const float* __restrict__ P,
                              const float* __restrict__ AT,
                              const float* __restrict__ BT,
                              float* __restrict__ C)
{
    __shared__ __align__(16) float smem[N + 16];   // 16.06 KB, reused per stage
    __shared__ unsigned s_gen0;

    const int tid  = threadIdx.x;
    const int bid  = blockIdx.x;
    const int warp = tid >> 5;
    const int lane = tid & 31;

    // Snapshot the generation counter. No block can advance it before every
    // block has arrived at barrier 1, and every block reads s_gen0 before
    // arriving — so the snapshot is race-free. Relative compares survive the
    // counter growing across graph replays.
    if (tid == 0) s_gen0 = *(volatile unsigned*)&g_bar_gen[0];
    __syncthreads();

    unsigned nbar = 0;

#define GRID_BAR() do {                                                       \
        nbar++;                                                               \
        __syncthreads();                                                      \
        if (tid == 0) {                                                       \
            __threadfence();                                                  \
            unsigned _a = atomicAdd(&g_bar_count[0], 1u) + 1u;                \
            if (_a == NBLK) {                                                 \
                atomicExch(&g_bar_count[0], 0u);                              \
                __threadfence();                                              \
                atomicAdd(&g_bar_gen[0], 1u);                                 \
            } else {                                                          \
                while (*(volatile unsigned*)&g_bar_gen[0] - s_gen0 < nbar) {} \
                __threadfence();                                              \
            }                                                                 \
        }                                                                     \
        __syncthreads();                                                      \
    } while (0)

    // ---------------- Prep: g_Kh = (half)(P^2) --------------------------
    {
        const float4* p4  = reinterpret_cast<const float4*>(P);
        uint4*        kh4 = reinterpret_cast<uint4*>(g_Kh);
        const size_t total = (size_t)N * N / 8;                 // uint4 units
        for (size_t u = (size_t)bid * (total / NBLK) + tid;
             u < (size_t)(bid + 1) * (total / NBLK); u += NTHR) {
            float4 a = p4[2 * u];
            float4 b = p4[2 * u + 1];
            __half2 h0 = __floats2half2_rn(a.x * a.x, a.y * a.y);
            __half2 h1 = __floats2half2_rn(a.z * a.z, a.w * a.w);
            __half2 h2 = __floats2half2_rn(b.x * b.x, b.y * b.y);
            __half2 h3 = __floats2half2_rn(b.z * b.z, b.w * b.w);
            uint4 o;
            o.x = *reinterpret_cast<unsigned*>(&h0);
            o.y = *reinterpret_cast<unsigned*>(&h1);
            o.z = *reinterpret_cast<unsigned*>(&h2);
            o.w = *reinterpret_cast<unsigned*>(&h3);
            kh4[u] = o;
        }
    }
    GRID_BAR();

    // ---------------- 21 fixed-point iterations -------------------------
    for (int it = 0; it < NITER; it++) {
        // Stage A: AF[i] = AT[i] / (1 + Kh[i,:] . BF)
        // 16 rows/block (2 per warp); BF staged in shared.
        {
            float4* sbf4 = reinterpret_cast<float4*>(smem);
            if (it == 0) {
                const float4* src = reinterpret_cast<const float4*>(BT);
                for (int i = tid; i < N / 4; i += NTHR) sbf4[i] = src[i];
            } else {
                const float4* src = reinterpret_cast<const float4*>(g_BF);
                for (int i = tid; i < N / 4; i += NTHR) sbf4[i] = __ldcg(src + i);
            }
            __syncthreads();

            #pragma unroll
            for (int rr = 0; rr < 2; rr++) {
                const int row = bid * 16 + warp * 2 + rr;
                const uint4* prow =
                    reinterpret_cast<const uint4*>(g_Kh + ((size_t)row << 12));
                float acc = 0.f;
                #pragma unroll
                for (int j = lane; j < N / 8; j += 32) {     // 16 trips, 16B each
                    uint4 v = prow[j];                        // immutable -> L1 ok
                    const float* b = &smem[j * 8];
                    float2 f0 = __half22float2(*reinterpret_cast<__half2*>(&v.x));
                    float2 f1 = __half22float2(*reinterpret_cast<__half2*>(&v.y));
                    float2 f2 = __half22float2(*reinterpret_cast<__half2*>(&v.z));
                    float2 f3 = __half22float2(*reinterpret_cast<__half2*>(&v.w));
                    acc = fmaf(f0.x, b[0], acc);
                    acc = fmaf(f0.y, b[1], acc);
                    acc = fmaf(f1.x, b[2], acc);
                    acc = fmaf(f1.y, b[3], acc);
                    acc = fmaf(f2.x, b[4], acc);
                    acc = fmaf(f2.y, b[5], acc);
                    acc = fmaf(f3.x, b[6], acc);
                    acc = fmaf(f3.y, b[7], acc);
                }
                #pragma unroll
                for (int o = 16; o > 0; o >>= 1)
                    acc += __shfl_xor_sync(0xFFFFFFFFu, acc, o);
                if (lane == 0) __stcg(&g_AF[row], AT[row] / (1.0f + acc));
            }
        }
        GRID_BAR();

        // Stage B: tmp[cy][j] = sum_{i in chunk cy} AF[i] * Kh[i][j]
        // block = (cx = bid&15 col-tile, cy = bid>>4 row-chunk)
        {
            const int cx = bid & 15, cy = bid >> 4;
            const int colBase = cx * COL_TILE;
            const int rowBase = cy * CHUNK_ROWS;
            float* sAF  = smem;            // 256 floats
            float* sAcc = smem + 256;      // 8 x 256 floats

            if (tid < CHUNK_ROWS) sAF[tid] = __ldcg(&g_AF[rowBase + tid]);
            __syncthreads();

            float acc[8];
            #pragma unroll
            for (int k = 0; k < 8; k++) acc[k] = 0.f;

            #pragma unroll 4
            for (int s = 0; s < CHUNK_ROWS / 8; s++) {       // 32 trips
                const int r = warp + 8 * s;
                const float a = sAF[r];
                uint4 v = *reinterpret_cast<const uint4*>(
                    g_Kh + (((size_t)(rowBase + r)) << 12) + colBase + 8 * lane);
                float2 f0 = __half22float2(*reinterpret_cast<__half2*>(&v.x));
                float2 f1 = __half22float2(*reinterpret_cast<__half2*>(&v.y));
                float2 f2 = __half22float2(*reinterpret_cast<__half2*>(&v.z));
                float2 f3 = __half22float2(*reinterpret_cast<__half2*>(&v.w));
                acc[0] = fmaf(a, f0.x, acc[0]);
                acc[1] = fmaf(a, f0.y, acc[1]);
                acc[2] = fmaf(a, f1.x, acc[2]);
                acc[3] = fmaf(a, f1.y, acc[3]);
                acc[4] = fmaf(a, f2.x, acc[4]);
                acc[5] = fmaf(a, f2.y, acc[5]);
                acc[6] = fmaf(a, f3.x, acc[6]);
                acc[7] = fmaf(a, f3.y, acc[7]);
            }
            #pragma unroll
            for (int k = 0; k < 8; k++) sAcc[warp * 256 + lane * 8 + k] = acc[k];
            __syncthreads();

            float s = 0.f;                                    // fixed order
            #pragma unroll
            for (int w = 0; w < 8; w++) s += sAcc[w * 256 + tid];
            __stcg(&g_tmp[cy * N + colBase + tid], s);
        }
        GRID_BAR();

        // Stage C: BF[j] = BT[j] / (1 + sum_cy tmp[cy][j])  — 16 blocks work.
        if (bid < 16) {
            const int j = bid * 256 + tid;
            float s = 0.f;
            #pragma unroll
            for (int c = 0; c < ROW_CHUNKS; c++) s += __ldcg(&g_tmp[c * N + j]);
            __stcg(&g_BF[j], BT[j] / (1.0f + s));
        }
        GRID_BAR();
    }

    // ---------------- Output: C = P^2 * AF[:,None] * BF[None,:] ---------
    {
        float4* sbf4 = reinterpret_cast<float4*>(smem);
        const float4* src = reinterpret_cast<const float4*>(g_BF);
        for (int i = tid; i < N / 4; i += NTHR) sbf4[i] = __ldcg(src + i);
        if (tid < 16) smem[N + tid] = __ldcg(&g_AF[bid * 16 + tid]);  // 16 rows
        __syncthreads();

        const size_t base = (size_t)bid * 16 * (N / 4);   // float4 index of row block
        const float4* p4 = reinterpret_cast<const float4*>(P) + base;
        float4*       c4 = reinterpret_cast<float4*>(C) + base;

        #pragma unroll 4
        for (int t = tid; t < 16 * (N / 4); t += NTHR) {  // 64 trips
            const int row_l = t >> 10;
            const int col4  = t & 1023;
            const float  a = smem[N + row_l];
            const float4 p = p4[t];
            const float4 b = sbf4[col4];
            float4 o;
            o.x = p.x * p.x * a * b.x;
            o.y = p.y * p.y * a * b.y;
            o.z = p.z * p.z * a * b.z;
            o.w = p.w * p.w * a * b.w;
            c4[t] = o;
        }
    }
#undef GRID_BAR
}

// ---------------------------------------------------------------------------
// ONE kernel launch — one graph node. No sync/alloc/memcpy. 256 blocks of 256
// threads; __launch_bounds__(256,2) guarantees 2 CTAs/SM (296 slots >= 256),
// so all blocks are co-resident and the software grid barrier cannot deadlock.
// ---------------------------------------------------------------------------
extern "C" void kernel_launch(void* const* d_in, const int* in_sizes, int n_in,
                              void* d_out, int out_size)
{
    const float* AT = (const float*)d_in[0];   // [4096]
    const float* BT = (const float*)d_in[1];   // [4096]
    const float* P  = (const float*)d_in[2];   // [4096, 4096]
    float* C = (float*)d_out;                  // [4096, 4096]

    competitive_solve_kernel<<<NBLK, NTHR>>>(P, AT, BT, C);
}

// round 10
// speedup vs baseline: 1.2550x; 1.2550x over previous
#include <cuda_runtime.h>
#include <cuda_fp16.h>

// CompetitiveLayer: 21 x { AF = AT/(1+K@BF); BF = BT/(1+AF@K) }, K = param^2,
// then C = param^2 * AF[:,None] * BF[None,:].
//
// R9 lesson: a software GRID barrier (3.5us, skew-bound) is worse than a
// kernel boundary (~2us). But LOCAL last-arrival sync among the 16 blocks of
// one column tile is cheap. So: back to multi-kernel (R8, 318.6us), with
// finalize_bf fused into col_mv via threadfence-reduction — 64 -> 44 nodes.
//
// K streamed as a one-time fp16 copy (32 MB, L2-resident): halves iteration
// traffic; final C uses exact fp32 param^2 (rel_err ~6e-6, gate is 1e-3).

#define N        4096
#define NITER    21
#define ROW_CHUNKS 16
#define CHUNK_ROWS (N / ROW_CHUNKS)   // 256
#define COL_TILE   256

// Scratch — __device__ globals (no cudaMalloc allowed)
__device__ __half   g_Kh[(size_t)N * N];   // fp16 param^2 (32 MB)
__device__ float    g_AF[N];
__device__ float    g_BF[N];
__device__ float    g_tmp[ROW_CHUNKS * N];
__device__ unsigned g_cnt[16 * 32];        // per-cx arrival counter, 128B apart
                                           // monotonic: no reset, replay-safe

// ---------------------------------------------------------------------------
// Prep: g_Kh[i][j] = (half)(P[i][j]^2).  One thread = 8 elements.
// ---------------------------------------------------------------------------
__global__ __launch_bounds__(256, 4)
void prep_kh_kernel(const float* __restrict__ P)
{
    const size_t idx = (size_t)blockIdx.x * 256 + threadIdx.x;  // unit: 8 floats
    const float4* p4 = reinterpret_cast<const float4*>(P);
    float4 a = p4[2 * idx];
    float4 b = p4[2 * idx + 1];

    __half2 h0 = __floats2half2_rn(a.x * a.x, a.y * a.y);
    __half2 h1 = __floats2half2_rn(a.z * a.z, a.w * a.w);
    __half2 h2 = __floats2half2_rn(b.x * b.x, b.y * b.y);
    __half2 h3 = __floats2half2_rn(b.z * b.z, b.w * b.w);

    uint4 out;
    out.x = *reinterpret_cast<unsigned*>(&h0);
    out.y = *reinterpret_cast<unsigned*>(&h1);
    out.z = *reinterpret_cast<unsigned*>(&h2);
    out.w = *reinterpret_cast<unsigned*>(&h3);
    reinterpret_cast<uint4*>(g_Kh)[idx] = out;
}

// ---------------------------------------------------------------------------
// Row matvec: AF[i] = AT[i] / (1 + Kh[i,:] . BF)
// 1 warp per row, 8 rows per 256-thread block, BF staged in shared.
// BF was written by the previous kernel -> plain loads are safe (L1 flushed
// per launch). grid = 512.
// ---------------------------------------------------------------------------
__global__ __launch_bounds__(256, 2)
void row_mv_kernel(const float* __restrict__ AT,
                   const float* __restrict__ BT,
                   int use_bt)
{
    __shared__ float sBF[N];   // 16 KB

    const int tid = threadIdx.x;
    const float* BFin = use_bt ? BT : g_BF;
    const float4* bf4 = reinterpret_cast<const float4*>(BFin);
    float4* sbf4 = reinterpret_cast<float4*>(sBF);
    #pragma unroll
    for (int i = tid; i < N / 4; i += 256) sbf4[i] = bf4[i];
    __syncthreads();

    const int warp = tid >> 5;
    const int lane = tid & 31;
    const int row  = blockIdx.x * 8 + warp;

    const uint4* prow = reinterpret_cast<const uint4*>(g_Kh + ((size_t)row << 12));

    float acc = 0.f;
    #pragma unroll 8
    for (int j = lane; j < N / 8; j += 32) {      // 16 trips, 16B each
        uint4 v = prow[j];
        const float* b = &sBF[j * 8];
        float2 f0 = __half22float2(*reinterpret_cast<__half2*>(&v.x));
        float2 f1 = __half22float2(*reinterpret_cast<__half2*>(&v.y));
        float2 f2 = __half22float2(*reinterpret_cast<__half2*>(&v.z));
        float2 f3 = __half22float2(*reinterpret_cast<__half2*>(&v.w));
        acc = fmaf(f0.x, b[0], acc);
        acc = fmaf(f0.y, b[1], acc);
        acc = fmaf(f1.x, b[2], acc);
        acc = fmaf(f1.y, b[3], acc);
        acc = fmaf(f2.x, b[4], acc);
        acc = fmaf(f2.y, b[5], acc);
        acc = fmaf(f3.x, b[6], acc);
        acc = fmaf(f3.y, b[7], acc);
    }
    #pragma unroll
    for (int o = 16; o > 0; o >>= 1) acc += __shfl_xor_sync(0xFFFFFFFFu, acc, o);

    if (lane == 0) g_AF[row] = AT[row] / (1.0f + acc);
}

// ---------------------------------------------------------------------------
// Col matvec + fused finalize (threadfence reduction):
//   partial: tmp[cy][j] = sum_{i in chunk cy} AF[i] * Kh[i][j]
//   the LAST block to finish a column tile cx reduces all 16 partials in
//   fixed c-order (deterministic) and writes BF[j] = BT[j]/(1+sum).
// grid = (16 cx, 16 cy). Cross-block data goes through L2 (__stcg/__ldcg).
// ---------------------------------------------------------------------------
__global__ __launch_bounds__(256, 4)
void col_mv_kernel(const float* __restrict__ BT)
{
    __shared__ float sAF[CHUNK_ROWS];     // 1 KB
    __shared__ float sAcc[8 * COL_TILE];  // 8 KB
    __shared__ int   sLast;

    const int tid     = threadIdx.x;
    const int warp    = tid >> 5;
    const int lane    = tid & 31;
    const int cx      = blockIdx.x;
    const int cy      = blockIdx.y;
    const int colBase = cx * COL_TILE;
    const int rowBase = cy * CHUNK_ROWS;

    if (tid < CHUNK_ROWS) sAF[tid] = g_AF[rowBase + tid];   // prev-kernel data
    __syncthreads();

    float acc[8];
    #pragma unroll
    for (int k = 0; k < 8; k++) acc[k] = 0.f;

    #pragma unroll 4
    for (int s = 0; s < CHUNK_ROWS / 8; s++) {    // 32 trips
        const int r = warp + 8 * s;
        const float a = sAF[r];
        uint4 v = *reinterpret_cast<const uint4*>(
            g_Kh + (((size_t)(rowBase + r)) << 12) + colBase + 8 * lane);
        float2 f0 = __half22float2(*reinterpret_cast<__half2*>(&v.x));
        float2 f1 = __half22float2(*reinterpret_cast<__half2*>(&v.y));
        float2 f2 = __half22float2(*reinterpret_cast<__half2*>(&v.z));
        float2 f3 = __half22float2(*reinterpret_cast<__half2*>(&v.w));
        acc[0] = fmaf(a, f0.x, acc[0]);
        acc[1] = fmaf(a, f0.y, acc[1]);
        acc[2] = fmaf(a, f1.x, acc[2]);
        acc[3] = fmaf(a, f1.y, acc[3]);
        acc[4] = fmaf(a, f2.x, acc[4]);
        acc[5] = fmaf(a, f2.y, acc[5]);
        acc[6] = fmaf(a, f3.x, acc[6]);
        acc[7] = fmaf(a, f3.y, acc[7]);
    }

    #pragma unroll
    for (int k = 0; k < 8; k++) sAcc[warp * 256 + lane * 8 + k] = acc[k];
    __syncthreads();

    // Fixed-order cross-warp reduce; thread t owns column colBase + t.
    float s = 0.f;
    #pragma unroll
    for (int w = 0; w < 8; w++) s += sAcc[w * 256 + tid];
    __stcg(&g_tmp[cy * N + colBase + tid], s);   // L2, bypass L1

    // Publish our partial, then find out if we're the 16th arriver for cx.
    __threadfence();
    __syncthreads();
    if (tid == 0) {
        unsigned old = atomicAdd(&g_cnt[cx * 32], 1u);  // monotonic, no reset
        sLast = ((old & 15u) == 15u);
    }
    __syncthreads();

    if (sLast) {
        __threadfence();   // acquire: order tmp reads after the atomic
        const int j = colBase + tid;
        float t = 0.f;
        #pragma unroll
        for (int c = 0; c < ROW_CHUNKS; c++) t += __ldcg(&g_tmp[c * N + j]);
        g_BF[j] = BT[j] / (1.0f + t);
    }
}

// ---------------------------------------------------------------------------
// Output: C[i][j] = param[i][j]^2 * AF[i] * BF[j]  — exact fp32 K.
// ---------------------------------------------------------------------------
__global__ __launch_bounds__(256, 4)
void compute_c_kernel(const float* __restrict__ P, float* __restrict__ C)
{
    const size_t idx = (size_t)blockIdx.x * 256 + threadIdx.x;  // float4 index
    const int row  = (int)(idx >> 10);
    const int col4 = (int)(idx & 1023);

    const float a  = g_AF[row];
    const float4 p = reinterpret_cast<const float4*>(P)[idx];
    const float4 b = *reinterpret_cast<const float4*>(&g_BF[col4 * 4]);

    float4 o;
    o.x = p.x * p.x * a * b.x;
    o.y = p.y * p.y * a * b.y;
    o.z = p.z * p.z * a * b.z;
    o.w = p.w * p.w * a * b.w;
    reinterpret_cast<float4*>(C)[idx] = o;
}

// ---------------------------------------------------------------------------
// Launch: prep + 21 x {rowMV, colMV(+finalize)} + C = 44 graph nodes.
// Default stream only; no sync, no alloc, no memcpy — graph-capturable.
// ---------------------------------------------------------------------------
extern "C" void kernel_launch(void* const* d_in, const int* in_sizes, int n_in,
                              void* d_out, int out_size)
{
    const float* AT = (const float*)d_in[0];   // [4096]
    const float* BT = (const float*)d_in[1];   // [4096]
    const float* P  = (const float*)d_in[2];   // [4096, 4096]
    float* C = (float*)d_out;                  // [4096, 4096]

    prep_kh_kernel<<<((size_t)N * N / 8) / 256, 256>>>(P);

    const dim3 colGrid(16, ROW_CHUNKS);        // (cx, cy)

    for (int it = 0; it < NITER; it++) {
        row_mv_kernel<<<N / 8, 256>>>(AT, BT, it == 0 ? 1 : 0);
        col_mv_kernel<<<colGrid, 256>>>(BT);
    }
    compute_c_kernel<<<((size_t)N * (N / 4)) / 256, 256>>>(P, C);
}